// round 17
// baseline (speedup 1.0000x reference)
#include <cuda_runtime.h>
#include <cuda_fp16.h>
#include <math.h>
#include <stdint.h>

// Problem shape (fixed)
static const int BATCH = 4;
static const int LQ    = 2048;
static const int SK    = 2048;
static const int D     = 1024;

// Static arena (no allocs). Layout in __half units:
//   A1h @ 0    (8M)  : Q hi            [8192,1024]
//   A1l @ 8M   (8M)  : Q lo
//   Bh  @ 16M  (8M)  : W^T / K / V^T hi
//   Bl  @ 24M  (8M)  : lo (unused for V)
//   A2h @ 32M  (16M) : QW hi -> P (single fp16)  [8192,1024] then [8192,2048]
//   A2l @ 48M  (16M) : QW lo
#define MH (1024*1024)
__device__ __half g_arena[(size_t)64 * MH];

// ---------------------------------------------------------------------------
// helpers
// ---------------------------------------------------------------------------
__device__ __forceinline__ uint32_t smem_u32(const void* p) {
    uint32_t a;
    asm("{ .reg .u64 t; cvta.to.shared.u64 t, %1; cvt.u32.u64 %0, t; }"
        : "=r"(a) : "l"(p));
    return a;
}

__device__ __forceinline__ void cp_async16(uint32_t s, const void* g) {
    asm volatile("cp.async.cg.shared.global [%0], [%1], 16;" :: "r"(s), "l"(g));
}

__device__ __forceinline__ uint32_t ld32(const __half* p) {
    return *reinterpret_cast<const uint32_t*>(p);
}

__device__ __forceinline__ void mma_f16(float* c, const uint32_t* a,
                                        const uint32_t* b) {
    asm volatile(
        "mma.sync.aligned.m16n8k16.row.col.f32.f16.f16.f32 "
        "{%0,%1,%2,%3}, {%4,%5,%6,%7}, {%8,%9}, {%0,%1,%2,%3};"
        : "+f"(c[0]), "+f"(c[1]), "+f"(c[2]), "+f"(c[3])
        : "r"(a[0]), "r"(a[1]), "r"(a[2]), "r"(a[3]), "r"(b[0]), "r"(b[1]));
}

__device__ __forceinline__ void split_h(float x, __half& h, __half& l) {
    h = __float2half_rn(x);
    l = __float2half_rn(x - __half2float(h));
}

// ---------------------------------------------------------------------------
// Elementwise fp16 split: h = f16(x), l = f16(x - h).  n % 1024 == 0.
// ---------------------------------------------------------------------------
__global__ __launch_bounds__(256)
void split_f16(const float4* __restrict__ in, __half2* __restrict__ h,
               __half2* __restrict__ l)
{
    const long i = (long)blockIdx.x * 256 + threadIdx.x;
    float4 x = in[i];
    __half hx, lx, hy, ly, hz, lz, hw, lw;
    split_h(x.x, hx, lx); split_h(x.y, hy, ly);
    split_h(x.z, hz, lz); split_h(x.w, hw, lw);
    h[2 * i]     = __halves2half2(hx, hy);
    h[2 * i + 1] = __halves2half2(hz, hw);
    l[2 * i]     = __halves2half2(lx, ly);
    l[2 * i + 1] = __halves2half2(lz, lw);
}

// ---------------------------------------------------------------------------
// Transpose + fp16 split: out_{h,l}[c][r] = split(in[r][c]).  32x32 tiles.
// ol == nullptr -> write hi only (single-fp16 consumer).
// ---------------------------------------------------------------------------
__global__ __launch_bounds__(256)
void transpose_split(const float* __restrict__ in, __half* __restrict__ oh,
                     __half* __restrict__ ol, int R, int Cn, long sIn, long sOut)
{
    __shared__ float t[32][33];
    const float* ib = in + (long)blockIdx.z * sIn;
    __half* ohb = oh + (long)blockIdx.z * sOut;
    __half* olb = ol ? ol + (long)blockIdx.z * sOut : nullptr;
    const int r0 = blockIdx.y * 32, c0 = blockIdx.x * 32;
    const int tx = threadIdx.x & 31, ty = threadIdx.x >> 5;   // 32x8
    #pragma unroll
    for (int i = 0; i < 32; i += 8)
        t[ty + i][tx] = ib[(long)(r0 + ty + i) * Cn + c0 + tx];
    __syncthreads();
    #pragma unroll
    for (int i = 0; i < 32; i += 8) {
        float x = t[tx][ty + i];
        long o = (long)(c0 + ty + i) * R + r0 + tx;
        if (olb) {
            __half h, l;
            split_h(x, h, l);
            ohb[o] = h;
            olb[o] = l;
        } else {
            ohb[o] = __float2half_rn(x);
        }
    }
}

// ---------------------------------------------------------------------------
// fp16 multi-term GEMM (NT) via mma.sync.m16n8k16:
// TERMS=3: C = (Ah+Al)(Bh+Bl)^T   (hh + hl + lh)   tiles {Ah,Al,Bh,Bl}
// TERMS=2: C = Ah(Bh+Bl)^T        (h  + l)         tiles {Ah,Bh,Bl}
// TERMS=1: C = Ah Bh^T                             tiles {Ah,Bh}
// CTA 128x128, BK=32, 8 warps (2m x 4n), warp tile 64x32.
// STAGES-deep cp.async pipeline; __launch_bounds__(256,2) -> 2 CTAs/SM.
// Issue order hh[all j], hl[all j], lh[all j] spaces RAW accumulates apart.
// SMEM rows padded to 40 halves (80 B).
// SPLITOUT: write C as fp16 hi/lo pair instead of fp32.
// ---------------------------------------------------------------------------
template <int TERMS, int STAGES, bool SPLITOUT>
__global__ __launch_bounds__(256, 2)
void mma3gemm(const __half* __restrict__ Ah, const __half* __restrict__ Al,
              const __half* __restrict__ Bh, const __half* __restrict__ Bl,
              float* __restrict__ C, __half* __restrict__ Ch,
              __half* __restrict__ Cl, int K, int ldc,
              long sA, long sB, long sC)
{
    constexpr int TILES = (TERMS == 3) ? 4 : (TERMS == 2 ? 3 : 2);
    constexpr int STAGE_H = TILES * 5120;           // halves per stage
    constexpr int STAGE_B = STAGE_H * 2;            // bytes per stage

    extern __shared__ __half smh[];
    const uint32_t sbase = smem_u32(smh);

    const int tid = threadIdx.x, lane = tid & 31, wid = tid >> 5;
    const int warp_m = wid & 1, warp_n = wid >> 1;
    const int gid = lane >> 2, tnum = lane & 3;
    const int row0 = blockIdx.y * 128, col0 = blockIdx.x * 128;
    const long zb = blockIdx.z;

    const __half* gT[TILES];
    gT[0] = Ah + zb * sA + (long)row0 * K;
    if (TERMS == 3) {
        gT[1] = Al + zb * sA + (long)row0 * K;
        gT[2] = Bh + zb * sB + (long)col0 * K;
        gT[3] = Bl + zb * sB + (long)col0 * K;
    } else if (TERMS == 2) {
        gT[1] = Bh + zb * sB + (long)col0 * K;
        gT[2] = Bl + zb * sB + (long)col0 * K;
    } else {
        gT[1] = Bh + zb * sB + (long)col0 * K;
    }

    const int niter = K >> 5;

    auto load_stage = [&](int it, int stage) {
        const int kk = it * 32;
        #pragma unroll
        for (int t = 0; t < 2 * TILES; t++) {
            int c    = t * 256 + tid;
            int tile = c >> 9;             // 512 cp.async per tile
            int row  = (c >> 2) & 127;
            int seg  = c & 3;              // 4 x 8-half segments per row
            const __half* g = gT[tile] + (long)row * K + kk + seg * 8;
            uint32_t s = sbase +
                (uint32_t)(stage * STAGE_B + tile * 10240 + row * 80 + seg * 16);
            cp_async16(s, g);
        }
    };

    float acc[4][4][4] = {};

    #pragma unroll
    for (int s = 0; s < STAGES; s++) {
        load_stage(s, s);
        asm volatile("cp.async.commit_group;" ::: "memory");
    }

    for (int it = 0; it < niter; ++it) {
        if (STAGES == 2)
            asm volatile("cp.async.wait_group 1;" ::: "memory");
        else
            asm volatile("cp.async.wait_group 2;" ::: "memory");
        __syncthreads();

        const int buf = it % STAGES;
        const __half* st  = smh + buf * STAGE_H;
        const __half* sAh = st;
        const __half* sAl = (TERMS == 3) ? st + 5120 : nullptr;
        const __half* sBh = (TERMS == 3) ? st + 10240 : st + 5120;
        const __half* sBl = (TERMS == 3) ? st + 15360 :
                            (TERMS == 2) ? st + 10240 : nullptr;

        #pragma unroll
        for (int k16 = 0; k16 < 2; k16++) {
            const int kb = k16 * 16 + 2 * tnum;   // first half of k-pair

            uint32_t bh[4][2], bl[4][2];
            #pragma unroll
            for (int j = 0; j < 4; j++) {
                const int n = warp_n * 32 + j * 8 + gid;
                const __half* pb = sBh + n * 40 + kb;
                bh[j][0] = ld32(pb);     bh[j][1] = ld32(pb + 8);
                if (TERMS >= 2) {
                    const __half* ql = sBl + n * 40 + kb;
                    bl[j][0] = ld32(ql); bl[j][1] = ld32(ql + 8);
                }
            }
            #pragma unroll
            for (int i = 0; i < 4; i++) {
                const int r = warp_m * 64 + i * 16 + gid;
                const __half* pa = sAh + r * 40 + kb;
                uint32_t ah[4];
                ah[0] = ld32(pa);        ah[1] = ld32(pa + 320);   // r+8
                ah[2] = ld32(pa + 8);    ah[3] = ld32(pa + 328);
                uint32_t al[4];
                if (TERMS == 3) {
                    const __half* qa = sAl + r * 40 + kb;
                    al[0] = ld32(qa);        al[1] = ld32(qa + 320);
                    al[2] = ld32(qa + 8);    al[3] = ld32(qa + 328);
                }
                // Issue groups: dependent accumulates into acc[i][j] are
                // spaced 4 instructions apart instead of back-to-back.
                #pragma unroll
                for (int j = 0; j < 4; j++)
                    mma_f16(acc[i][j], ah, bh[j]);       // hi*hi
                if (TERMS >= 2) {
                    #pragma unroll
                    for (int j = 0; j < 4; j++)
                        mma_f16(acc[i][j], ah, bl[j]);   // hi*lo
                }
                if (TERMS == 3) {
                    #pragma unroll
                    for (int j = 0; j < 4; j++)
                        mma_f16(acc[i][j], al, bh[j]);   // lo*hi
                }
            }
        }
        __syncthreads();
        if (it + STAGES < niter) load_stage(it + STAGES, it % STAGES);
        asm volatile("cp.async.commit_group;" ::: "memory");
    }

    // Epilogue
    #pragma unroll
    for (int i = 0; i < 4; i++) {
        const int r = row0 + warp_m * 64 + i * 16 + gid;
        #pragma unroll
        for (int j = 0; j < 4; j++) {
            const int cc = col0 + warp_n * 32 + j * 8 + 2 * tnum;
            if (SPLITOUT) {
                __half h0, l0, h1, l1;
                long o0 = (long)r * ldc + cc + zb * sC;
                long o1 = (long)(r + 8) * ldc + cc + zb * sC;
                split_h(acc[i][j][0], h0, l0);
                split_h(acc[i][j][1], h1, l1);
                *reinterpret_cast<__half2*>(Ch + o0) = __halves2half2(h0, h1);
                *reinterpret_cast<__half2*>(Cl + o0) = __halves2half2(l0, l1);
                split_h(acc[i][j][2], h0, l0);
                split_h(acc[i][j][3], h1, l1);
                *reinterpret_cast<__half2*>(Ch + o1) = __halves2half2(h0, h1);
                *reinterpret_cast<__half2*>(Cl + o1) = __halves2half2(l0, l1);
            } else {
                float* Cb = C + zb * sC;
                *reinterpret_cast<float2*>(&Cb[(long)r * ldc + cc]) =
                    make_float2(acc[i][j][0], acc[i][j][1]);
                *reinterpret_cast<float2*>(&Cb[(long)(r + 8) * ldc + cc]) =
                    make_float2(acc[i][j][2], acc[i][j][3]);
            }
        }
    }
}

// ---------------------------------------------------------------------------
// Masked row softmax (SK=2048) in place + fused single-fp16 P for the P@V
// GEMM. Mask is int32. All-masked row -> uniform 1/SK.
// ---------------------------------------------------------------------------
__global__ __launch_bounds__(256)
void softmax_split(float* __restrict__ S, const int* __restrict__ mask,
                   __half* __restrict__ Ph)
{
    const int row = blockIdx.x;
    const int b   = row / LQ;
    float* p = S + (long)row * SK;
    __half* ph = Ph + (long)row * SK;
    const int* m = mask + (long)b * SK;
    const int t = threadIdx.x;

    __shared__ float red[256];

    float vals[8];
    int mk[8];
    float mx = -INFINITY;
    #pragma unroll
    for (int i = 0; i < 8; i++) {
        const int c = t + i * 256;
        vals[i] = p[c];
        mk[i]   = m[c];
        if (mk[i]) mx = fmaxf(mx, vals[i]);
    }
    red[t] = mx; __syncthreads();
    for (int s = 128; s > 0; s >>= 1) {
        if (t < s) red[t] = fmaxf(red[t], red[t + s]);
        __syncthreads();
    }
    mx = red[0];
    __syncthreads();

    if (!isfinite(mx)) {
        const float u = 1.0f / (float)SK;
        const __half uh = __float2half_rn(u);
        #pragma unroll
        for (int i = 0; i < 8; i++) {
            p[t + i * 256]  = u;
            ph[t + i * 256] = uh;
        }
        return;
    }

    float sum = 0.f;
    #pragma unroll
    for (int i = 0; i < 8; i++) {
        float e = mk[i] ? expf(vals[i] - mx) : 0.f;
        vals[i] = e;
        sum += e;
    }
    red[t] = sum; __syncthreads();
    for (int s = 128; s > 0; s >>= 1) {
        if (t < s) red[t] += red[t + s];
        __syncthreads();
    }
    const float inv = 1.0f / red[0];
    #pragma unroll
    for (int i = 0; i < 8; i++) {
        const int c = t + i * 256;
        float pv = vals[i] * inv;
        p[c] = pv;
        ph[c] = __float2half_rn(pv);
    }
}

// ---------------------------------------------------------------------------
// kernel_launch
// Inputs: query, key, value, W, mask. Output: [output_value | score] fp32.
// ---------------------------------------------------------------------------
extern "C" void kernel_launch(void* const* d_in, const int* in_sizes, int n_in,
                              void* d_out, int out_size)
{
    const float* q    = (const float*)d_in[0];
    const float* kk   = (const float*)d_in[1];
    const float* v    = (const float*)d_in[2];
    const float* W    = (const float*)d_in[3];
    const int*   mask = (const int*)d_in[4];

    float* oval  = (float*)d_out;                       // [4,2048,1024]
    float* score = oval + (long)BATCH * LQ * D;         // [4,2048,2048]

    __half* arena = nullptr;
    cudaGetSymbolAddress((void**)&arena, g_arena);
    __half* A1h = arena;                                // 8M
    __half* A1l = arena + (long) 8 * MH;                // 8M
    __half* Bh  = arena + (long)16 * MH;                // 8M
    __half* Bl  = arena + (long)24 * MH;                // 8M
    __half* A2h = arena + (long)32 * MH;                // 16M
    __half* A2l = arena + (long)48 * MH;                // 16M

    const int SMEM3 = 2 * 40960;                        // 3-term, 2 stages
    const int SMEM1 = 3 * 20480;                        // 1-term, 3 stages
    static bool attr_set = false;
    if (!attr_set) {
        cudaFuncSetAttribute((const void*)mma3gemm<3, 2, true>,
            cudaFuncAttributeMaxDynamicSharedMemorySize, SMEM3);
        cudaFuncSetAttribute((const void*)mma3gemm<3, 2, false>,
            cudaFuncAttributeMaxDynamicSharedMemorySize, SMEM3);
        cudaFuncSetAttribute((const void*)mma3gemm<1, 3, false>,
            cudaFuncAttributeMaxDynamicSharedMemorySize, SMEM1);
        attr_set = true;
    }

    // ---- Phase 1: QW = Q @ W, result written directly as split halves ----
    split_f16<<<(BATCH * LQ * (long)D) / 1024, 256>>>(
        (const float4*)q, (__half2*)A1h, (__half2*)A1l);
    transpose_split<<<dim3(D / 32, D / 32, 1), 256>>>(W, Bh, Bl, D, D, 0, 0);
    mma3gemm<3, 2, true><<<dim3(D / 128, (BATCH * LQ) / 128, 1), 256, SMEM3>>>(
        A1h, A1l, Bh, Bl, nullptr, A2h, A2l, D, D, 0, 0, 0);

    // ---- Phase 2: S = QW @ K^T per batch ----
    split_f16<<<(BATCH * SK * (long)D) / 1024, 256>>>(
        (const float4*)kk, (__half2*)Bh, (__half2*)Bl);
    mma3gemm<3, 2, false><<<dim3(SK / 128, LQ / 128, BATCH), 256, SMEM3>>>(
        A2h, A2l, Bh, Bl, score, nullptr, nullptr, D, SK,
        (long)LQ * D, (long)SK * D, (long)LQ * SK);

    // ---- Phase 3: softmax (+fused fp16 P), then O = P @ V per batch ----
    softmax_split<<<BATCH * LQ, 256>>>(score, mask, A2h);
    transpose_split<<<dim3(D / 32, SK / 32, BATCH), 256>>>(
        v, Bh, nullptr, SK, D, (long)SK * D, (long)D * SK);
    mma3gemm<1, 3, false><<<dim3(D / 128, LQ / 128, BATCH), 256, SMEM1>>>(
        A2h, nullptr, Bh, nullptr, oval, nullptr, nullptr, SK, D,
        (long)LQ * SK, (long)D * SK, (long)LQ * D);
}